// round 1
// baseline (speedup 1.0000x reference)
#include <cuda_runtime.h>
#include <cstdint>

// Problem constants
#define BATCH 64
#define HIN   32
#define WIN   32
#define CH    3
#define T_STEPS 2700            // (32-2)*(32-2)*3
#define HID   128
#define PRE_N 32
#define VMAX  256
#define GATES 384               // 3*HID
#define IN_DIM 14               // 5*C - 1

// Scratch (device globals: allocation-free rule)
__device__ float g_xg[(size_t)BATCH * T_STEPS * GATES];   // ~253 MB
__device__ float g_hs[(size_t)BATCH * T_STEPS * HID];     // ~84 MB

// ---------------- packed f32x2 helpers ----------------
__device__ __forceinline__ unsigned long long ffma2(unsigned long long a,
                                                    unsigned long long b,
                                                    unsigned long long c) {
    unsigned long long d;
    asm("fma.rn.f32x2 %0, %1, %2, %3;" : "=l"(d) : "l"(a), "l"(b), "l"(c));
    return d;
}
__device__ __forceinline__ float2 unpack2(unsigned long long v) {
    float2 f;
    asm("mov.b64 {%0, %1}, %2;" : "=f"(f.x), "=f"(f.y) : "l"(v));
    return f;
}
__device__ __forceinline__ float sigmoidf_fast(float x) {
    return 1.0f / (1.0f + __expf(-x));
}
__device__ __forceinline__ float tanhf_fast(float x) {
    // 2*sigmoid(2x)-1 ; near-fp32 accuracy via MUFU EX2 + RCP
    return 2.0f / (1.0f + __expf(-2.0f * x)) - 1.0f;
}

// ---------------- kernel 0: zero output ----------------
__global__ void k_zero(float4* __restrict__ out, int n4) {
    int stride = gridDim.x * blockDim.x;
    for (int i = blockIdx.x * blockDim.x + threadIdx.x; i < n4; i += stride)
        out[i] = make_float4(0.f, 0.f, 0.f, 0.f);
}

// ---------------- kernel 1: gather + pre MLP + input gates ----------------
// one warp per (b, s) row; 8 warps / block; grid = 64*2700/8 = 21600
__global__ __launch_bounds__(256) void k_pre(
    const float* __restrict__ x,
    const float* __restrict__ Wpre,   // [32,14]
    const float* __restrict__ bpre,   // [32]
    const float* __restrict__ Wih,    // [384,32]
    const float* __restrict__ bih)    // [384]
{
    __shared__ float WihT[PRE_N * GATES];   // 49152 B (transposed: [p][g])
    for (int i = threadIdx.x; i < PRE_N * GATES; i += blockDim.x) {
        int g = i >> 5, p = i & 31;
        WihT[p * GATES + g] = Wih[i];
    }
    __syncthreads();

    int warp = threadIdx.x >> 5, lane = threadIdx.x & 31;
    int row = blockIdx.x * 8 + warp;
    if (row >= BATCH * T_STEPS) return;
    int b = row / T_STEPS;
    int s = row - b * T_STEPS;
    int c  = s % 3;
    int iw = (s / 3) % 30;
    int ih = s / 90;

    // Gather 14 features (lanes 0..13 hold one each)
    float val = 0.f;
    if (lane < IN_DIM) {
        if (lane < 12) {
            int g4 = lane / 3, ch = lane % 3;
            int dy = (g4 == 3) ? 1 : 0;
            int dx = (g4 == 3) ? 0 : g4;
            val = x[(((size_t)(b * CH + ch) * HIN) + (ih + dy)) * WIN + (iw + dx)];
        } else {
            int ch = lane - 12;   // ct channel 0 or 1
            val = (c > ch)
                ? x[(((size_t)(b * CH + ch) * HIN) + (ih + 1)) * WIN + (iw + 1)]
                : -1.0f;
        }
    }

    // pre[lane] = sigmoid(sum_l Wpre[lane,l]*inp[l] + bpre[lane])
    float acc = bpre[lane];
#pragma unroll
    for (int l = 0; l < IN_DIM; l++)
        acc = fmaf(Wpre[lane * IN_DIM + l], __shfl_sync(0xffffffffu, val, l), acc);
    float pre = sigmoidf_fast(acc);

    // xg[g] = sum_p Wih[g,p]*pre[p] + bih[g],   g = i*32 + lane
    float accs[12];
#pragma unroll
    for (int i = 0; i < 12; i++) accs[i] = bih[i * 32 + lane];
#pragma unroll
    for (int p = 0; p < PRE_N; p++) {
        float pv = __shfl_sync(0xffffffffu, pre, p);
        const float* wr = &WihT[p * GATES + lane];
#pragma unroll
        for (int i = 0; i < 12; i++)
            accs[i] = fmaf(wr[i * 32], pv, accs[i]);
    }
    float* o = g_xg + (size_t)row * GATES;
#pragma unroll
    for (int i = 0; i < 12; i++) o[i * 32 + lane] = accs[i];
}

// ---------------- kernel 2: sequential GRU, 1 CTA per batch element ----------------
__global__ __launch_bounds__(GATES, 1) void k_rnn(
    const float* __restrict__ Whh,   // [384,128]
    const float* __restrict__ bhh)   // [384]
{
    int b = blockIdx.x;
    int j = threadIdx.x;             // gate row 0..383

    __shared__ __align__(16) float h_sh[HID];
    __shared__ float g_sh[GATES];
    __shared__ float xg_sh[GATES];

    // Weight-stationary W_hh row j in registers, packed f32x2
    unsigned long long w2[64];
    {
        const ulonglong2* wr = (const ulonglong2*)(Whh + (size_t)j * HID);
#pragma unroll
        for (int k = 0; k < 32; k++) {
            ulonglong2 q = wr[k];
            w2[2 * k]     = q.x;
            w2[2 * k + 1] = q.y;
        }
    }
    float bj = bhh[j];

    if (j < HID) h_sh[j] = 0.f;

    const float* xgb = g_xg + (size_t)b * T_STEPS * GATES + j;
    float xg_cur = xgb[0];
    float xg_nxt = xgb[GATES];
    float* hsb = g_hs + (size_t)b * T_STEPS * HID;
    __syncthreads();

    for (int t = 0; t < T_STEPS; t++) {
        // hg[j] = W_hh[j,:] . h  (packed pairs, two accumulator chains)
        unsigned long long acc0 = 0ull, acc1 = 0ull;   // {0.f,0.f}
        const ulonglong2* h2 = (const ulonglong2*)h_sh;
#pragma unroll
        for (int k = 0; k < 32; k++) {
            ulonglong2 q = h2[k];
            acc0 = ffma2(w2[2 * k],     q.x, acc0);
            acc1 = ffma2(w2[2 * k + 1], q.y, acc1);
        }
        float2 a0 = unpack2(acc0), a1 = unpack2(acc1);
        g_sh[j]  = (a0.x + a0.y) + (a1.x + a1.y) + bj;
        xg_sh[j] = xg_cur;

        // rotate prefetch (depth 2)
        xg_cur = xg_nxt;
        if (t + 2 < T_STEPS) xg_nxt = xgb[(size_t)(t + 2) * GATES];

        __syncthreads();

        if (j < HID) {
            float r = sigmoidf_fast(xg_sh[j]           + g_sh[j]);
            float z = sigmoidf_fast(xg_sh[HID + j]     + g_sh[HID + j]);
            float n = tanhf_fast(xg_sh[2 * HID + j] + r * g_sh[2 * HID + j]);
            float hprev = h_sh[j];
            float hnew  = n + z * (hprev - n);      // (1-z)*n + z*h
            h_sh[j] = hnew;
            hsb[(size_t)t * HID + j] = hnew;
        }
        __syncthreads();
    }
}

// ---------------- kernel 3: output head GEMM + scatter into padded layout ----------------
// grid = 64*10 blocks; block handles 270 sequence rows in 9 tiles of 30.
// thread v (0..255) holds W_post[v,:] in registers.
__global__ __launch_bounds__(VMAX, 1) void k_post(
    const float* __restrict__ Wpost,   // [256,128]
    const float* __restrict__ bpost,   // [256]
    float* __restrict__ out)
{
    int blk = blockIdx.x;
    int b = blk / 10;
    int s0 = (blk % 10) * 270;
    int v = threadIdx.x;

    __shared__ __align__(16) float hs_sh[30 * HID];

    unsigned long long w2[64];
    {
        const ulonglong2* wr = (const ulonglong2*)(Wpost + (size_t)v * HID);
#pragma unroll
        for (int k = 0; k < 32; k++) {
            ulonglong2 q = wr[k];
            w2[2 * k]     = q.x;
            w2[2 * k + 1] = q.y;
        }
    }
    float bias = bpost[v];
    const float* hsb = g_hs + (size_t)b * T_STEPS * HID;

    for (int tile = 0; tile < 9; tile++) {
        int sbase = s0 + tile * 30;
        __syncthreads();
        for (int i = v; i < 30 * HID; i += VMAX)
            hs_sh[i] = hsb[(size_t)sbase * HID + i];
        __syncthreads();

        for (int r = 0; r < 30; r++) {
            unsigned long long acc0 = 0ull, acc1 = 0ull;
            const ulonglong2* h2 = (const ulonglong2*)(hs_sh + r * HID);
#pragma unroll
            for (int k = 0; k < 32; k++) {
                ulonglong2 q = h2[k];
                acc0 = ffma2(w2[2 * k],     q.x, acc0);
                acc1 = ffma2(w2[2 * k + 1], q.y, acc1);
            }
            float2 a0 = unpack2(acc0), a1 = unpack2(acc1);
            float o = (a0.x + a0.y) + (a1.x + a1.y) + bias;

            int s  = sbase + r;
            int c  = s % 3;
            int iw = (s / 3) % 30;
            int ih = s / 90;
            size_t idx = ((((size_t)(b * CH + c) * HIN) + (ih + 1)) * WIN + (iw + 1))
                         * (size_t)VMAX + v;
            out[idx] = o;
        }
    }
}

// ---------------- launch ----------------
extern "C" void kernel_launch(void* const* d_in, const int* in_sizes, int n_in,
                              void* d_out, int out_size) {
    const float* x      = (const float*)d_in[0];
    const float* W_pre  = (const float*)d_in[1];
    const float* b_pre  = (const float*)d_in[2];
    const float* W_ih   = (const float*)d_in[3];
    const float* b_ih   = (const float*)d_in[4];
    const float* W_hh   = (const float*)d_in[5];
    const float* b_hh   = (const float*)d_in[6];
    const float* W_post = (const float*)d_in[7];
    const float* b_post = (const float*)d_in[8];
    float* out = (float*)d_out;

    int n4 = out_size / 4;
    k_zero<<<4096, 256>>>((float4*)out, n4);
    k_pre<<<(BATCH * T_STEPS) / 8, 256>>>(x, W_pre, b_pre, W_ih, b_ih);
    k_rnn<<<BATCH, GATES>>>(W_hh, b_hh);
    k_post<<<BATCH * 10, VMAX>>>(W_post, b_post, out);
}